// round 3
// baseline (speedup 1.0000x reference)
#include <cuda_runtime.h>

#define NN 50000
#define NE 800000
#define NET (NE + NN)
#define HEADS 4
#define HID 64
#define D1 256            // HEADS*HID
#define IND 128
#define EMB 128
#define NG 64

// ---------------- scratch (static device globals; no allocation) ----------------
__device__ __align__(16) float    g_h1[(size_t)NN * D1];
__device__ __align__(16) float    g_acc1[(size_t)NN * D1];   // layer1 agg, then in-place ELU
__device__ __align__(16) float    g_h2[(size_t)NN * EMB];
__device__ __align__(16) float    g_acc2[(size_t)NN * EMB];
__device__ __align__(16) float    g_as1[NN * HEADS];
__device__ __align__(16) float    g_ad1[NN * HEADS];
__device__ __align__(16) float    g_z1[NN * HEADS];
__device__ __align__(16) unsigned g_m1[NN * HEADS];
__device__ __align__(16) float    g_as2[NN];
__device__ __align__(16) float    g_ad2[NN];
__device__ __align__(16) float    g_z2[NN];
__device__ __align__(16) unsigned g_m2[NN];
__device__ __align__(16) float    g_pool[NG * EMB];
__device__ __align__(16) float    g_cnt[NG];
// clean int32 edge list (self-loops appended) + batch vector
__device__ __align__(16) int      g_src[NET];
__device__ __align__(16) int      g_dst[NET];
__device__ __align__(16) int      g_batch[NN];

// ---------------- helpers ----------------
__device__ __forceinline__ unsigned fenc(float f) {
    unsigned u = __float_as_uint(f);
    return (u & 0x80000000u) ? ~u : (u | 0x80000000u);
}
__device__ __forceinline__ float fdec(unsigned u) {
    return __uint_as_float((u & 0x80000000u) ? (u & 0x7fffffffu) : ~u);
}
__device__ __forceinline__ float elu1(float x)  { return x > 0.f ? x : expm1f(x); }
__device__ __forceinline__ float lrelu(float x) { return x > 0.f ? x : 0.2f * x; }

__device__ __forceinline__ void red4(float* p, float a, float b, float c, float d) {
    asm volatile("red.global.add.v4.f32 [%0], {%1, %2, %3, %4};"
                 :: "l"(p), "f"(a), "f"(b), "f"(c), "f"(d) : "memory");
}

// ---------------- prep: dtype-robust index materialization ----------------
// edge_index may be int32 (JAX default: x64 disabled coerces jnp.int64->int32)
// or genuine int64. Detect on-device: int64 little-endian positive values have
// zero high words at odd int32 positions; int32 node-ids there are ~never all 0.
__global__ __launch_bounds__(256) void prep_kernel(const void* ei_raw, const void* b_raw) {
    const int*       e32 = (const int*)ei_raw;
    const long long* e64 = (const long long*)ei_raw;
    bool is64 = true;
#pragma unroll
    for (int i = 0; i < 16; i++) is64 &= (e32[2 * i + 1] == 0);

    int idx = blockIdx.x * blockDim.x + threadIdx.x;
    if (idx < NET) {
        int s, d;
        if (idx < NE) {
            if (is64) { s = (int)e64[idx]; d = (int)e64[NE + idx]; }
            else      { s = e32[idx];      d = e32[NE + idx]; }
        } else {
            s = d = idx - NE;   // self-loop
        }
        g_src[idx] = s;
        g_dst[idx] = d;
    }
    if (idx < NN) {
        g_batch[idx] = is64 ? (int)((const long long*)b_raw)[idx]
                            : ((const int*)b_raw)[idx];
    }
}

// ---------------- zero scratch ----------------
__global__ void zero_all() {
    long long stride = (long long)gridDim.x * blockDim.x;
    long long t = (long long)blockIdx.x * blockDim.x + threadIdx.x;
    for (long long i = t; i < (long long)NN * D1; i += stride)  g_acc1[i] = 0.f;
    for (long long i = t; i < (long long)NN * EMB; i += stride) g_acc2[i] = 0.f;
    for (long long i = t; i < NG * EMB; i += stride)            g_pool[i] = 0.f;
    for (long long i = t; i < NG; i += stride)                  g_cnt[i]  = 0.f;
}

// ---------------- fp32 GEMM: C[M,N] = A[M,K] @ B[K,N] ----------------
__global__ __launch_bounds__(256) void gemm_kernel(
    const float* __restrict__ A, const float* __restrict__ B, float* __restrict__ C,
    int M, int N, int K)
{
    __shared__ float As[16][129];
    __shared__ float Bs[16][64];

    int tid = threadIdx.x;
    int rowBase = blockIdx.x * 128;
    int colBase = blockIdx.y * 64;
    int ty = tid >> 4;
    int tx = tid & 15;

    float acc[8][4];
#pragma unroll
    for (int i = 0; i < 8; i++)
#pragma unroll
        for (int j = 0; j < 4; j++) acc[i][j] = 0.f;

    for (int k0 = 0; k0 < K; k0 += 16) {
#pragma unroll
        for (int it = 0; it < 8; it++) {
            int idx = tid + 256 * it;
            int r = idx >> 4, kk = idx & 15;
            int row = rowBase + r;
            As[kk][r] = (row < M) ? A[(long long)row * K + k0 + kk] : 0.f;
        }
#pragma unroll
        for (int it = 0; it < 4; it++) {
            int idx = tid + 256 * it;
            int kk = idx >> 6, cc = idx & 63;
            Bs[kk][cc] = B[(long long)(k0 + kk) * N + colBase + cc];
        }
        __syncthreads();
#pragma unroll
        for (int kk = 0; kk < 16; kk++) {
            float ra[8], rb[4];
#pragma unroll
            for (int i = 0; i < 8; i++) ra[i] = As[kk][ty + 16 * i];
#pragma unroll
            for (int j = 0; j < 4; j++) rb[j] = Bs[kk][tx + 16 * j];
#pragma unroll
            for (int i = 0; i < 8; i++)
#pragma unroll
                for (int j = 0; j < 4; j++) acc[i][j] += ra[i] * rb[j];
        }
        __syncthreads();
    }
#pragma unroll
    for (int i = 0; i < 8; i++) {
        int row = rowBase + ty + 16 * i;
        if (row < M) {
#pragma unroll
            for (int j = 0; j < 4; j++)
                C[(long long)row * N + colBase + tx + 16 * j] = acc[i][j];
        }
    }
}

// ---------------- layer 1 ----------------
__global__ __launch_bounds__(256) void alphas1_kernel(
    const float* __restrict__ asrc, const float* __restrict__ adst)
{
    int warp = (blockIdx.x * blockDim.x + threadIdx.x) >> 5;
    int lane = threadIdx.x & 31;
    if (warp >= NN) return;
    const float4* hp = (const float4*)(g_h1 + (long long)warp * D1);
    int h = lane >> 3, sub = lane & 7;
    float4 v0 = hp[lane * 2], v1 = hp[lane * 2 + 1];
    const float4* ap = (const float4*)(asrc + h * HID + sub * 8);
    const float4* dp = (const float4*)(adst + h * HID + sub * 8);
    float4 a0 = ap[0], a1 = ap[1], d0 = dp[0], d1 = dp[1];
    float s = v0.x*a0.x + v0.y*a0.y + v0.z*a0.z + v0.w*a0.w
            + v1.x*a1.x + v1.y*a1.y + v1.z*a1.z + v1.w*a1.w;
    float d = v0.x*d0.x + v0.y*d0.y + v0.z*d0.z + v0.w*d0.w
            + v1.x*d1.x + v1.y*d1.y + v1.z*d1.z + v1.w*d1.w;
#pragma unroll
    for (int off = 4; off; off >>= 1) {
        s += __shfl_down_sync(0xffffffffu, s, off);
        d += __shfl_down_sync(0xffffffffu, d, off);
    }
    if (sub == 0) {
        g_as1[warp * 4 + h] = s;
        g_ad1[warp * 4 + h] = d;
        g_m1[warp * 4 + h] = 0u;
        g_z1[warp * 4 + h] = 0.f;
    }
}

__global__ __launch_bounds__(256) void edgemax1_kernel() {
    int idx = blockIdx.x * blockDim.x + threadIdx.x;
    if (idx >= NET * HEADS) return;
    int e = idx >> 2, h = idx & 3;
    int s = g_src[e], d = g_dst[e];
    float v = lrelu(g_as1[s * 4 + h] + g_ad1[d * 4 + h]);
    atomicMax(&g_m1[d * 4 + h], fenc(v));
}

__global__ __launch_bounds__(256) void edgesum1_kernel() {
    int idx = blockIdx.x * blockDim.x + threadIdx.x;
    if (idx >= NET * HEADS) return;
    int e = idx >> 2, h = idx & 3;
    int s = g_src[e], d = g_dst[e];
    float v = lrelu(g_as1[s * 4 + h] + g_ad1[d * 4 + h]);
    atomicAdd(&g_z1[d * 4 + h], __expf(v - fdec(g_m1[d * 4 + h])));
}

// one warp per edge; 256 floats -> 8 per lane (2 float4), head = lane/8
__global__ __launch_bounds__(256) void msg1_kernel() {
    int warp = (blockIdx.x * blockDim.x + threadIdx.x) >> 5;
    int lane = threadIdx.x & 31;
    if (warp >= NET) return;
    int s = g_src[warp], d = g_dst[warp];
    int h = lane >> 3;
    float e = lrelu(g_as1[s * 4 + h] + g_ad1[d * 4 + h]);
    float alpha = __expf(e - fdec(g_m1[d * 4 + h])) / g_z1[d * 4 + h];
    const float4* hp = (const float4*)(g_h1 + (long long)s * D1);
    float4 v0 = hp[lane * 2], v1 = hp[lane * 2 + 1];
    float* o = g_acc1 + (long long)d * D1 + lane * 8;
    red4(o,     v0.x * alpha, v0.y * alpha, v0.z * alpha, v0.w * alpha);
    red4(o + 4, v1.x * alpha, v1.y * alpha, v1.z * alpha, v1.w * alpha);
}

__global__ __launch_bounds__(256) void finalize1_kernel(const float* __restrict__ b1) {
    int i = blockIdx.x * blockDim.x + threadIdx.x;
    if (i >= NN * D1 / 4) return;
    float4 v = ((float4*)g_acc1)[i];
    float4 bb = ((const float4*)b1)[i & (D1 / 4 - 1)];
    v.x = elu1(v.x + bb.x); v.y = elu1(v.y + bb.y);
    v.z = elu1(v.z + bb.z); v.w = elu1(v.w + bb.w);
    ((float4*)g_acc1)[i] = v;
}

// ---------------- layer 2 ----------------
__global__ __launch_bounds__(256) void alphas2_kernel(
    const float* __restrict__ asrc, const float* __restrict__ adst)
{
    int warp = (blockIdx.x * blockDim.x + threadIdx.x) >> 5;
    int lane = threadIdx.x & 31;
    if (warp >= NN) return;
    float4 v = ((const float4*)(g_h2 + (long long)warp * EMB))[lane];
    float4 a = ((const float4*)asrc)[lane];
    float4 d = ((const float4*)adst)[lane];
    float s  = v.x*a.x + v.y*a.y + v.z*a.z + v.w*a.w;
    float dd = v.x*d.x + v.y*d.y + v.z*d.z + v.w*d.w;
#pragma unroll
    for (int off = 16; off; off >>= 1) {
        s  += __shfl_down_sync(0xffffffffu, s, off);
        dd += __shfl_down_sync(0xffffffffu, dd, off);
    }
    if (lane == 0) {
        g_as2[warp] = s; g_ad2[warp] = dd;
        g_m2[warp] = 0u; g_z2[warp] = 0.f;
    }
}

__global__ __launch_bounds__(256) void edgemax2_kernel() {
    int e = blockIdx.x * blockDim.x + threadIdx.x;
    if (e >= NET) return;
    int s = g_src[e], d = g_dst[e];
    float v = lrelu(g_as2[s] + g_ad2[d]);
    atomicMax(&g_m2[d], fenc(v));
}

__global__ __launch_bounds__(256) void edgesum2_kernel() {
    int e = blockIdx.x * blockDim.x + threadIdx.x;
    if (e >= NET) return;
    int s = g_src[e], d = g_dst[e];
    float v = lrelu(g_as2[s] + g_ad2[d]);
    atomicAdd(&g_z2[d], __expf(v - fdec(g_m2[d])));
}

// one warp per edge; 128 floats -> 4 per lane (1 float4)
__global__ __launch_bounds__(256) void msg2_kernel() {
    int warp = (blockIdx.x * blockDim.x + threadIdx.x) >> 5;
    int lane = threadIdx.x & 31;
    if (warp >= NET) return;
    int s = g_src[warp], d = g_dst[warp];
    float e = lrelu(g_as2[s] + g_ad2[d]);
    float alpha = __expf(e - fdec(g_m2[d])) / g_z2[d];
    float4 v = ((const float4*)(g_h2 + (long long)s * EMB))[lane];
    float* o = g_acc2 + (long long)d * EMB + lane * 4;
    red4(o, v.x * alpha, v.y * alpha, v.z * alpha, v.w * alpha);
}

__global__ __launch_bounds__(256) void finalize2_kernel(const float* __restrict__ b2) {
    int i = blockIdx.x * blockDim.x + threadIdx.x;
    if (i >= NN * EMB) return;
    int n = i >> 7, c = i & 127;
    float v = elu1(g_acc2[i] + b2[c]);
    int b = g_batch[n];
    atomicAdd(&g_pool[b * EMB + c], v);
    if (c == 0) atomicAdd(&g_cnt[b], 1.f);
}

__global__ __launch_bounds__(256) void final_div_kernel(float* __restrict__ out) {
    int i = blockIdx.x * blockDim.x + threadIdx.x;
    if (i >= NG * EMB) return;
    out[i] = g_pool[i] / fmaxf(g_cnt[i >> 7], 1.f);
}

// ---------------- launcher ----------------
extern "C" void kernel_launch(void* const* d_in, const int* in_sizes, int n_in,
                              void* d_out, int out_size)
{
    const float* x      = (const float*)d_in[0];
    const void*  ei     = d_in[1];           // int32 or int64 — detected on device
    // d_in[2] edge_weight: unused by reference
    const void*  batch  = d_in[3];
    const float* W1     = (const float*)d_in[4];
    const float* a_src1 = (const float*)d_in[5];
    const float* a_dst1 = (const float*)d_in[6];
    const float* b1     = (const float*)d_in[7];
    const float* W2     = (const float*)d_in[8];
    const float* a_src2 = (const float*)d_in[9];
    const float* a_dst2 = (const float*)d_in[10];
    const float* b2     = (const float*)d_in[11];
    float*       out    = (float*)d_out;

    float *p_h1, *p_acc1, *p_h2;
    cudaGetSymbolAddress((void**)&p_h1,   g_h1);
    cudaGetSymbolAddress((void**)&p_acc1, g_acc1);
    cudaGetSymbolAddress((void**)&p_h2,   g_h2);

    prep_kernel<<<(NET + 255) / 256, 256>>>(ei, batch);
    zero_all<<<2048, 256>>>();

    // layer 1
    gemm_kernel<<<dim3((NN + 127) / 128, D1 / 64), 256>>>(x, W1, p_h1, NN, D1, IND);
    alphas1_kernel<<<(NN + 7) / 8, 256>>>(a_src1, a_dst1);
    edgemax1_kernel<<<(NET * HEADS + 255) / 256, 256>>>();
    edgesum1_kernel<<<(NET * HEADS + 255) / 256, 256>>>();
    msg1_kernel<<<(NET + 7) / 8, 256>>>();
    finalize1_kernel<<<(NN * D1 / 4 + 255) / 256, 256>>>(b1);

    // layer 2
    gemm_kernel<<<dim3((NN + 127) / 128, EMB / 64), 256>>>(p_acc1, W2, p_h2, NN, EMB, D1);
    alphas2_kernel<<<(NN + 7) / 8, 256>>>(a_src2, a_dst2);
    edgemax2_kernel<<<(NET + 255) / 256, 256>>>();
    edgesum2_kernel<<<(NET + 255) / 256, 256>>>();
    msg2_kernel<<<(NET + 7) / 8, 256>>>();
    finalize2_kernel<<<(NN * EMB + 255) / 256, 256>>>(b2);

    // pooled mean
    final_div_kernel<<<(NG * EMB + 255) / 256, 256>>>(out);
}

// round 4
// speedup vs baseline: 1.6174x; 1.6174x over previous
#include <cuda_runtime.h>

#define NN 50000
#define NE 800000
#define NET (NE + NN)
#define HEADS 4
#define HID 64
#define D1 256            // HEADS*HID
#define IND 128
#define EMB 128
#define NG 64

typedef unsigned long long ull;

// ---------------- scratch ----------------
__device__ __align__(16) float g_h1[(size_t)NN * D1];
__device__ __align__(16) float g_act1[(size_t)NN * D1];   // elu(agg1 + b1)
__device__ __align__(16) float g_h2[(size_t)NN * EMB];
__device__ __align__(16) float g_as1[NN * HEADS];
__device__ __align__(16) float g_ad1[NN * HEADS];
__device__ __align__(16) float g_as2[NN];
__device__ __align__(16) float g_ad2[NN];
__device__ __align__(16) float g_pool[NG * EMB];
__device__ __align__(16) float g_cnt[NG];
__device__ __align__(16) int   g_src[NET];
__device__ __align__(16) int   g_dst[NET];
__device__ __align__(16) int   g_batch[NN];
__device__ __align__(16) int   g_rowptr[NN + 1];
__device__ __align__(16) int   g_wp[NN];
__device__ __align__(16) int   g_csrc[NET];   // src ids grouped by dst

// ---------------- helpers ----------------
__device__ __forceinline__ float elu1(float x)  { return x > 0.f ? x : expm1f(x); }
__device__ __forceinline__ float lrelu(float x) { return x > 0.f ? x : 0.2f * x; }

__device__ __forceinline__ void red4(float* p, float a, float b, float c, float d) {
    asm volatile("red.global.add.v4.f32 [%0], {%1, %2, %3, %4};"
                 :: "l"(p), "f"(a), "f"(b), "f"(c), "f"(d) : "memory");
}
__device__ __forceinline__ void ffma2(ull& d, ull a, ull b) {
    asm("fma.rn.f32x2 %0, %1, %2, %0;" : "+l"(d) : "l"(a), "l"(b));
}
__device__ __forceinline__ ull pack2(float lo, float hi) {
    ull r; asm("mov.b64 %0, {%1, %2};" : "=l"(r) : "f"(lo), "f"(hi)); return r;
}
__device__ __forceinline__ void unpack2(float& lo, float& hi, ull v) {
    asm("mov.b64 {%0, %1}, %2;" : "=f"(lo), "=f"(hi) : "l"(v));
}

// ---------------- prep: dtype-robust indices + zero small scratch ----------------
__global__ __launch_bounds__(256) void prep_kernel(const void* ei_raw, const void* b_raw) {
    const int*       e32 = (const int*)ei_raw;
    const long long* e64 = (const long long*)ei_raw;
    bool is64 = true;
#pragma unroll
    for (int i = 0; i < 16; i++) is64 &= (e32[2 * i + 1] == 0);

    int idx = blockIdx.x * blockDim.x + threadIdx.x;
    if (idx < NET) {
        int s, d;
        if (idx < NE) {
            if (is64) { s = (int)e64[idx]; d = (int)e64[NE + idx]; }
            else      { s = e32[idx];      d = e32[NE + idx]; }
        } else { s = d = idx - NE; }
        g_src[idx] = s;
        g_dst[idx] = d;
    }
    if (idx < NN) {
        g_batch[idx] = is64 ? (int)((const long long*)b_raw)[idx] : ((const int*)b_raw)[idx];
        g_wp[idx] = 0;
    }
    if (idx < NG * EMB) g_pool[idx] = 0.f;
    if (idx < NG)       g_cnt[idx]  = 0.f;
}

// degree count (into g_wp) + per-graph node counts
__global__ __launch_bounds__(256) void deg_kernel() {
    int idx = blockIdx.x * blockDim.x + threadIdx.x;
    if (idx < NET) atomicAdd(&g_wp[g_dst[idx]], 1);
    if (idx < NN)  atomicAdd(&g_cnt[g_batch[idx]], 1.f);
}

// single-block exclusive scan of degrees -> rowptr; g_wp becomes write cursor
__global__ __launch_bounds__(1024) void scan_kernel() {
    __shared__ int part[1024];
    int t = threadIdx.x;
    const int CH = (NN + 1023) / 1024;   // 49
    int beg = t * CH, end = min(beg + CH, NN);
    int sum = 0;
    for (int i = beg; i < end; i++) sum += g_wp[i];
    part[t] = sum;
    __syncthreads();
    for (int off = 1; off < 1024; off <<= 1) {
        int v = (t >= off) ? part[t - off] : 0;
        __syncthreads();
        part[t] += v;
        __syncthreads();
    }
    int run = (t == 0) ? 0 : part[t - 1];
    for (int i = beg; i < end; i++) {
        int c = g_wp[i];
        g_rowptr[i] = run;
        g_wp[i] = run;
        run += c;
    }
    if (t == 1023) g_rowptr[NN] = run;
}

__global__ __launch_bounds__(256) void fill_kernel() {
    int e = blockIdx.x * blockDim.x + threadIdx.x;
    if (e >= NET) return;
    int pos = atomicAdd(&g_wp[g_dst[e]], 1);
    g_csrc[pos] = g_src[e];
}

// ---------------- f32x2 GEMM: C[M,N] = A[M,K] @ B[K,N] ----------------
// BM=128, BN=128, BK=8, 256 threads, 8x8 per thread (M-paired f32x2 accum).
__global__ __launch_bounds__(256) void gemm_kernel(
    const float* __restrict__ A, const float* __restrict__ B, float* __restrict__ C,
    int M, int N, int K)
{
    __shared__ float As[8][132];   // transposed A tile, 528B rows (16B-aligned)
    __shared__ float Bs[8][132];

    int tid = threadIdx.x;
    int rowBase = blockIdx.x * 128;
    int colBase = blockIdx.y * 128;
    int tx = tid & 15;             // n-tile 0..15
    int ty = tid >> 4;             // m-tile 0..15

    ull acc[4][8];
#pragma unroll
    for (int p = 0; p < 4; p++)
#pragma unroll
        for (int j = 0; j < 8; j++) acc[p][j] = 0ull;

    int arow = rowBase + (tid >> 1);
    int akoff = (tid & 1) * 4;
    int brow = tid >> 5;             // 0..7
    int bcol = colBase + (tid & 31) * 4;

    for (int k0 = 0; k0 < K; k0 += 8) {
        float4 av = make_float4(0.f, 0.f, 0.f, 0.f);
        if (arow < M) av = *(const float4*)(A + (long long)arow * K + k0 + akoff);
        float4 bv = *(const float4*)(B + (long long)(k0 + brow) * N + bcol);
        int r = tid >> 1;
        As[akoff + 0][r] = av.x; As[akoff + 1][r] = av.y;
        As[akoff + 2][r] = av.z; As[akoff + 3][r] = av.w;
        *(float4*)&Bs[brow][(tid & 31) * 4] = bv;
        __syncthreads();

#pragma unroll
        for (int kk = 0; kk < 8; kk++) {
            ulonglong2 a01 = *(const ulonglong2*)&As[kk][ty * 8];
            ulonglong2 a23 = *(const ulonglong2*)&As[kk][ty * 8 + 4];
            float4 b0 = *(const float4*)&Bs[kk][tx * 8];
            float4 b1 = *(const float4*)&Bs[kk][tx * 8 + 4];
            ull rb[8];
            rb[0] = pack2(b0.x, b0.x); rb[1] = pack2(b0.y, b0.y);
            rb[2] = pack2(b0.z, b0.z); rb[3] = pack2(b0.w, b0.w);
            rb[4] = pack2(b1.x, b1.x); rb[5] = pack2(b1.y, b1.y);
            rb[6] = pack2(b1.z, b1.z); rb[7] = pack2(b1.w, b1.w);
            ull ra[4] = {a01.x, a01.y, a23.x, a23.y};
#pragma unroll
            for (int p = 0; p < 4; p++)
#pragma unroll
                for (int j = 0; j < 8; j++) ffma2(acc[p][j], ra[p], rb[j]);
        }
        __syncthreads();
    }

#pragma unroll
    for (int p = 0; p < 4; p++) {
        float lo[8], hi[8];
#pragma unroll
        for (int j = 0; j < 8; j++) unpack2(lo[j], hi[j], acc[p][j]);
        int m0 = rowBase + ty * 8 + 2 * p;
        long long cbase = (long long)m0 * N + colBase + tx * 8;
        if (m0 < M) {
            *(float4*)(C + cbase)     = make_float4(lo[0], lo[1], lo[2], lo[3]);
            *(float4*)(C + cbase + 4) = make_float4(lo[4], lo[5], lo[6], lo[7]);
        }
        if (m0 + 1 < M) {
            *(float4*)(C + cbase + N)     = make_float4(hi[0], hi[1], hi[2], hi[3]);
            *(float4*)(C + cbase + N + 4) = make_float4(hi[4], hi[5], hi[6], hi[7]);
        }
    }
}

// ---------------- attention logits ----------------
__global__ __launch_bounds__(256) void alphas1_kernel(
    const float* __restrict__ asrc, const float* __restrict__ adst)
{
    int warp = (blockIdx.x * blockDim.x + threadIdx.x) >> 5;
    int lane = threadIdx.x & 31;
    if (warp >= NN) return;
    const float4* hp = (const float4*)(g_h1 + (long long)warp * D1);
    int h = lane >> 3, sub = lane & 7;
    float4 v0 = hp[lane * 2], v1 = hp[lane * 2 + 1];
    const float4* ap = (const float4*)(asrc + h * HID + sub * 8);
    const float4* dp = (const float4*)(adst + h * HID + sub * 8);
    float4 a0 = ap[0], a1 = ap[1], d0 = dp[0], d1 = dp[1];
    float s = v0.x*a0.x + v0.y*a0.y + v0.z*a0.z + v0.w*a0.w
            + v1.x*a1.x + v1.y*a1.y + v1.z*a1.z + v1.w*a1.w;
    float d = v0.x*d0.x + v0.y*d0.y + v0.z*d0.z + v0.w*d0.w
            + v1.x*d1.x + v1.y*d1.y + v1.z*d1.z + v1.w*d1.w;
#pragma unroll
    for (int off = 4; off; off >>= 1) {
        s += __shfl_down_sync(0xffffffffu, s, off);
        d += __shfl_down_sync(0xffffffffu, d, off);
    }
    if (sub == 0) {
        g_as1[warp * 4 + h] = s;
        g_ad1[warp * 4 + h] = d;
    }
}

__global__ __launch_bounds__(256) void alphas2_kernel(
    const float* __restrict__ asrc, const float* __restrict__ adst)
{
    int warp = (blockIdx.x * blockDim.x + threadIdx.x) >> 5;
    int lane = threadIdx.x & 31;
    if (warp >= NN) return;
    float4 v = ((const float4*)(g_h2 + (long long)warp * EMB))[lane];
    float4 a = ((const float4*)asrc)[lane];
    float4 d = ((const float4*)adst)[lane];
    float s  = v.x*a.x + v.y*a.y + v.z*a.z + v.w*a.w;
    float dd = v.x*d.x + v.y*d.y + v.z*d.z + v.w*d.w;
#pragma unroll
    for (int off = 16; off; off >>= 1) {
        s  += __shfl_down_sync(0xffffffffu, s, off);
        dd += __shfl_down_sync(0xffffffffu, dd, off);
    }
    if (lane == 0) { g_as2[warp] = s; g_ad2[warp] = dd; }
}

// ---------------- CSR aggregation (warp per dst node) ----------------
// layer 1: z + weighted sum in-pass (softmax w/o max-sub: exp args are O(1)),
// fused bias + ELU. No atomics, no zeroing.
__global__ __launch_bounds__(256) void agg1_kernel(const float* __restrict__ b1) {
    int d = (blockIdx.x * blockDim.x + threadIdx.x) >> 5;
    int lane = threadIdx.x & 31;
    if (d >= NN) return;
    int h = lane >> 3;
    float ad = g_ad1[d * 4 + h];
    int beg = g_rowptr[d], end = g_rowptr[d + 1];
    float z = 0.f;
    float4 a0 = make_float4(0.f, 0.f, 0.f, 0.f);
    float4 a1 = make_float4(0.f, 0.f, 0.f, 0.f);
    for (int i = beg; i < end; i++) {
        int s = g_csrc[i];
        float w = __expf(lrelu(g_as1[s * 4 + h] + ad));
        z += w;
        const float4* hp = (const float4*)(g_h1 + (long long)s * D1);
        float4 v0 = hp[lane * 2], v1 = hp[lane * 2 + 1];
        a0.x += w * v0.x; a0.y += w * v0.y; a0.z += w * v0.z; a0.w += w * v0.w;
        a1.x += w * v1.x; a1.y += w * v1.y; a1.z += w * v1.z; a1.w += w * v1.w;
    }
    float inv = 1.f / z;
    const float4* bb = (const float4*)(b1 + lane * 8);
    float4 c0 = bb[0], c1 = bb[1];
    float4 o0, o1;
    o0.x = elu1(a0.x * inv + c0.x); o0.y = elu1(a0.y * inv + c0.y);
    o0.z = elu1(a0.z * inv + c0.z); o0.w = elu1(a0.w * inv + c0.w);
    o1.x = elu1(a1.x * inv + c1.x); o1.y = elu1(a1.y * inv + c1.y);
    o1.z = elu1(a1.z * inv + c1.z); o1.w = elu1(a1.w * inv + c1.w);
    float4* op = (float4*)(g_act1 + (long long)d * D1);
    op[lane * 2] = o0; op[lane * 2 + 1] = o1;
}

// layer 2: single head; fused bias + ELU + pooled accumulation.
__global__ __launch_bounds__(256) void agg2_kernel(const float* __restrict__ b2) {
    int d = (blockIdx.x * blockDim.x + threadIdx.x) >> 5;
    int lane = threadIdx.x & 31;
    if (d >= NN) return;
    float ad = g_ad2[d];
    int beg = g_rowptr[d], end = g_rowptr[d + 1];
    float z = 0.f;
    float4 a = make_float4(0.f, 0.f, 0.f, 0.f);
    for (int i = beg; i < end; i++) {
        int s = g_csrc[i];
        float w = __expf(lrelu(g_as2[s] + ad));
        z += w;
        float4 v = ((const float4*)(g_h2 + (long long)s * EMB))[lane];
        a.x += w * v.x; a.y += w * v.y; a.z += w * v.z; a.w += w * v.w;
    }
    float inv = 1.f / z;
    float4 c = ((const float4*)b2)[lane];
    float o0 = elu1(a.x * inv + c.x), o1 = elu1(a.y * inv + c.y);
    float o2 = elu1(a.z * inv + c.z), o3 = elu1(a.w * inv + c.w);
    int b = g_batch[d];
    red4(&g_pool[b * EMB + lane * 4], o0, o1, o2, o3);
}

__global__ __launch_bounds__(256) void final_div_kernel(float* __restrict__ out) {
    int i = blockIdx.x * blockDim.x + threadIdx.x;
    if (i >= NG * EMB) return;
    out[i] = g_pool[i] / fmaxf(g_cnt[i >> 7], 1.f);
}

// ---------------- launcher ----------------
extern "C" void kernel_launch(void* const* d_in, const int* in_sizes, int n_in,
                              void* d_out, int out_size)
{
    const float* x      = (const float*)d_in[0];
    const void*  ei     = d_in[1];
    const void*  batch  = d_in[3];
    const float* W1     = (const float*)d_in[4];
    const float* a_src1 = (const float*)d_in[5];
    const float* a_dst1 = (const float*)d_in[6];
    const float* b1     = (const float*)d_in[7];
    const float* W2     = (const float*)d_in[8];
    const float* a_src2 = (const float*)d_in[9];
    const float* a_dst2 = (const float*)d_in[10];
    const float* b2     = (const float*)d_in[11];
    float*       out    = (float*)d_out;

    float *p_h1, *p_act1, *p_h2;
    cudaGetSymbolAddress((void**)&p_h1,   g_h1);
    cudaGetSymbolAddress((void**)&p_act1, g_act1);
    cudaGetSymbolAddress((void**)&p_h2,   g_h2);

    // CSR build (shared by both layers)
    prep_kernel<<<(NET + 255) / 256, 256>>>(ei, batch);
    deg_kernel<<<(NET + 255) / 256, 256>>>();
    scan_kernel<<<1, 1024>>>();
    fill_kernel<<<(NET + 255) / 256, 256>>>();

    // layer 1
    gemm_kernel<<<dim3((NN + 127) / 128, D1 / 128), 256>>>(x, W1, p_h1, NN, D1, IND);
    alphas1_kernel<<<(NN + 7) / 8, 256>>>(a_src1, a_dst1);
    agg1_kernel<<<(NN + 7) / 8, 256>>>(b1);

    // layer 2
    gemm_kernel<<<dim3((NN + 127) / 128, EMB / 128), 256>>>(p_act1, W2, p_h2, NN, EMB, D1);
    alphas2_kernel<<<(NN + 7) / 8, 256>>>(a_src2, a_dst2);
    agg2_kernel<<<(NN + 7) / 8, 256>>>(b2);

    final_div_kernel<<<(NG * EMB + 255) / 256, 256>>>(out);
}